// round 11
// baseline (speedup 1.0000x reference)
#include <cuda_runtime.h>
#include <cstdint>

// Problem constants
#define BB 2
#define TT 2048
#define CC 1024
#define HH 16
#define HS 64
#define NROWS (BB*TT)   // 4096
#define M3C  (3*CC)     // 3072
#define NX (NROWS*CC)
#define NW (M3C*CC)
#define NQKV (BB*HH*TT*HS)

// Scratch: Q (tf32-rounded), K/V pre-split hi/lo, GEMM presplit operands
__device__ float g_q  [NQKV];
__device__ float g_khi[NQKV], g_klo[NQKV];
__device__ float g_vhi[NQKV], g_vlo[NQKV];
__device__ float g_xhi[NX];
__device__ float g_whi[NW], g_wlo[NW];

// ===========================================================================
// Helpers (plain-sm_100-legal PTX)
// ===========================================================================
__device__ __forceinline__ uint32_t smem_u32(const void* p) {
    uint32_t a;
    asm("{ .reg .u64 t; cvta.to.shared.u64 t, %1; cvt.u32.u64 %0, t; }"
        : "=r"(a) : "l"(p));
    return a;
}

__device__ __forceinline__ void cp_async16(uint32_t dst, const void* src) {
    asm volatile("cp.async.cg.shared.global [%0], [%1], 16;"
                 :: "r"(dst), "l"(src));
}
#define CP_COMMIT() asm volatile("cp.async.commit_group;" ::: "memory")
#define CP_WAIT(n)  asm volatile("cp.async.wait_group %0;" :: "n"(n) : "memory")

__device__ __forceinline__ uint32_t tf32_of(float x) {
    uint32_t u;
    asm("cvt.rna.tf32.f32 %0, %1;" : "=r"(u) : "f"(x));
    return u;
}
__device__ __forceinline__ void split_tf32_f(float x, float& hi, float& lo) {
    uint32_t h;
    asm("cvt.rna.tf32.f32 %0, %1;" : "=r"(h) : "f"(x));
    hi = __uint_as_float(h);
    float r = x - hi;
    uint32_t l;
    asm("cvt.rna.tf32.f32 %0, %1;" : "=r"(l) : "f"(r));
    lo = __uint_as_float(l);
}

__device__ __forceinline__ void mma_tf32(float d[4], const uint32_t a[4],
                                         const uint32_t b[2]) {
    asm volatile(
        "mma.sync.aligned.m16n8k8.row.col.f32.tf32.tf32.f32 "
        "{%0,%1,%2,%3}, {%4,%5,%6,%7}, {%8,%9}, {%0,%1,%2,%3};"
        : "+f"(d[0]), "+f"(d[1]), "+f"(d[2]), "+f"(d[3])
        : "r"(a[0]), "r"(a[1]), "r"(a[2]), "r"(a[3]),
          "r"(b[0]), "r"(b[1]));
}

// ===========================================================================
// Kernel 0: pre-split. x -> hi only; W -> hi + lo.
// ===========================================================================
__global__ __launch_bounds__(256) void presplit_kernel(
    const float* __restrict__ x, const float* __restrict__ W)
{
    const size_t i4 = (size_t)blockIdx.x * 256 + threadIdx.x;
    if (i4 < NX / 4) {
        float4 v = ((const float4*)x)[i4];
        float4 h;
        h.x = __uint_as_float(tf32_of(v.x));
        h.y = __uint_as_float(tf32_of(v.y));
        h.z = __uint_as_float(tf32_of(v.z));
        h.w = __uint_as_float(tf32_of(v.w));
        ((float4*)g_xhi)[i4] = h;
    } else {
        const size_t off = i4 - NX / 4;
        float4 v = ((const float4*)W)[off];
        float4 h, l;
        split_tf32_f(v.x, h.x, l.x);
        split_tf32_f(v.y, h.y, l.y);
        split_tf32_f(v.z, h.z, l.z);
        split_tf32_f(v.w, h.w, l.w);
        ((float4*)g_whi)[off] = h;
        ((float4*)g_wlo)[off] = l;
    }
}

// ===========================================================================
// Kernel 1: QKV projection, 128x128 tile, 2-pass compensation.
// Epilogue now writes: Q tf32-rounded&scaled; K/V split into hi/lo gmem
// (one split, reused by all 16 q-tile CTAs of the attention kernel).
// ===========================================================================
#define GST 36
#define GBUF (128 * GST)                  // 4608 floats per matrix buffer
#define GEMM_SMEM (2 * 3 * GBUF * 4)      // 110592 bytes

__global__ __launch_bounds__(256, 2) void qkv_gemm_mma(const float* __restrict__ bias)
{
    extern __shared__ float sm[];
    const int tid = threadIdx.x, lane = tid & 31, warp = tid >> 5;
    const int wm = warp & 1, wn = warp >> 1;
    const int g = lane >> 2, tg = lane & 3;
    const int m0 = blockIdx.x * 128;
    const int n0 = blockIdx.y * 128;

    int r_[4], c_[4];
    #pragma unroll
    for (int i = 0; i < 4; i++) {
        int idx = tid + 256 * i;
        r_[i] = idx >> 3;
        c_[i] = (idx & 7) * 4;
    }
    const uint32_t smbase = smem_u32(sm);

    float acc[4][4][4];
    #pragma unroll
    for (int mt = 0; mt < 4; mt++)
        #pragma unroll
        for (int nt = 0; nt < 4; nt++)
            #pragma unroll
            for (int q = 0; q < 4; q++) acc[mt][nt][q] = 0.f;

    #define GEMM_ISSUE(ch) do { \
        const uint32_t _bs = smbase + ((ch) & 1) * (3 * GBUF) * 4; \
        const size_t _ko = (size_t)(ch) * 32; \
        const float* _xh = g_xhi + (size_t)m0 * CC + _ko; \
        const float* _wh = g_whi + (size_t)n0 * CC + _ko; \
        const float* _wl = g_wlo + (size_t)n0 * CC + _ko; \
        _Pragma("unroll") \
        for (int i = 0; i < 4; i++) { \
            const uint32_t _o = (uint32_t)(r_[i] * GST + c_[i]) * 4; \
            const size_t _s = (size_t)r_[i] * CC + c_[i]; \
            cp_async16(_bs + _o,                _xh + _s); \
            cp_async16(_bs + GBUF * 4 + _o,     _wh + _s); \
            cp_async16(_bs + 2 * GBUF * 4 + _o, _wl + _s); \
        } \
        CP_COMMIT(); \
    } while (0)

    GEMM_ISSUE(0);

    for (int ch = 0; ch < 32; ch++) {
        if (ch < 31) { GEMM_ISSUE(ch + 1); CP_WAIT(1); }
        else         { CP_WAIT(0); }
        __syncthreads();

        const float* Ah = sm + (ch & 1) * (3 * GBUF);
        const float* Bh = Ah + GBUF;
        const float* Bl = Ah + 2 * GBUF;

        #pragma unroll
        for (int ks = 0; ks < 4; ks++) {
            const int k0 = ks * 8;
            uint32_t ahi[4][4], bhi[4][2], blo[4][2];
            #pragma unroll
            for (int mt = 0; mt < 4; mt++) {
                const int rb = (wm * 64 + mt * 16 + g) * GST + k0 + tg;
                ahi[mt][0] = __float_as_uint(Ah[rb]);
                ahi[mt][1] = __float_as_uint(Ah[rb + 8 * GST]);
                ahi[mt][2] = __float_as_uint(Ah[rb + 4]);
                ahi[mt][3] = __float_as_uint(Ah[rb + 8 * GST + 4]);
            }
            #pragma unroll
            for (int nt = 0; nt < 4; nt++) {
                const int cb = (wn * 32 + nt * 8 + g) * GST + k0 + tg;
                bhi[nt][0] = __float_as_uint(Bh[cb]);
                bhi[nt][1] = __float_as_uint(Bh[cb + 4]);
                blo[nt][0] = __float_as_uint(Bl[cb]);
                blo[nt][1] = __float_as_uint(Bl[cb + 4]);
            }
            #pragma unroll
            for (int mt = 0; mt < 4; mt++)
                #pragma unroll
                for (int nt = 0; nt < 4; nt++) {
                    mma_tf32(acc[mt][nt], ahi[mt], bhi[nt]);
                    mma_tf32(acc[mt][nt], ahi[mt], blo[nt]);
                }
        }
        __syncthreads();
    }

    // Epilogue: bias + (Q: scale+round) / (K,V: hi/lo split), scatter.
    const int part = blockIdx.y >> 3;       // 0=q 1=k 2=v
    float* dhi = (part == 0) ? g_q : (part == 1) ? g_khi : g_vhi;
    float* dlo = (part == 1) ? g_klo : g_vlo;   // unused for part 0

    #pragma unroll
    for (int nt = 0; nt < 4; nt++) {
        const int n = n0 + wn * 32 + nt * 8 + 2 * tg;
        const int h = (n >> 6) & 15;
        const int d = n & 63;
        const float bb0 = __ldg(bias + n);
        const float bb1 = __ldg(bias + n + 1);
        #pragma unroll
        for (int mt = 0; mt < 4; mt++) {
            #pragma unroll
            for (int half = 0; half < 2; half++) {
                const int m = m0 + wm * 64 + mt * 16 + g + 8 * half;
                const int bi = m >> 11, t = m & 2047;
                const size_t ix = (((size_t)(bi * HH + h)) * TT + t) * HS + d;
                const float s0 = acc[mt][nt][2 * half]     + bb0;
                const float s1 = acc[mt][nt][2 * half + 1] + bb1;
                if (part == 0) {
                    float2 v;
                    v.x = __uint_as_float(tf32_of(s0 * 0.125f));
                    v.y = __uint_as_float(tf32_of(s1 * 0.125f));
                    *(float2*)(dhi + ix) = v;
                } else {
                    float2 h2, l2;
                    split_tf32_f(s0, h2.x, l2.x);
                    split_tf32_f(s1, h2.y, l2.y);
                    *(float2*)(dhi + ix) = h2;
                    *(float2*)(dlo + ix) = l2;
                }
            }
        }
    }
}

// ===========================================================================
// Kernel 2: causal flash attention, mma.sync tf32, 2-pass compensation.
// NEW vs R10: K/V arrive pre-split from gmem via direct cp.async (no per-tile
// split ALU, no LDG chains, no intermediate smem round-trip). Q arrives
// pre-rounded. MMA/softmax path byte-identical -> rel_err unchanged.
// ===========================================================================
#define KST 68
#define VST 72
#define PST 68
#define ATTN_SMEM ((64*KST*2 + 64*VST*2 + 128*PST) * 4)   // 106496 B

__global__ __launch_bounds__(256, 2) void attn_mma(float* __restrict__ out)
{
    extern __shared__ float asmem[];
    float* Khi = asmem;
    float* Klo = Khi + 64 * KST;
    float* Vhi = Klo + 64 * KST;
    float* Vlo = Vhi + 64 * VST;
    float* Ps  = Vlo + 64 * VST;

    const int tid = threadIdx.x, lane = tid & 31, wid = tid >> 5;
    const int g = lane >> 2, tg = lane & 3;
    const int qt = 15 - blockIdx.x;          // heavy CTAs first
    const int bh = blockIdx.y;
    const int q0 = qt * 128;
    const int wq = wid * 16;

    const float* Qg  = g_q   + (size_t)bh * (TT * HS);
    const float* Khg = g_khi + (size_t)bh * (TT * HS);
    const float* Klg = g_klo + (size_t)bh * (TT * HS);
    const float* Vhg = g_vhi + (size_t)bh * (TT * HS);
    const float* Vlg = g_vlo + (size_t)bh * (TT * HS);

    const uint32_t khi_b = smem_u32(Khi);
    const uint32_t klo_b = smem_u32(Klo);
    const uint32_t vhi_b = smem_u32(Vhi);
    const uint32_t vlo_b = smem_u32(Vlo);

    // Persistent Q fragments (pre-rounded tf32 bits, pre-scaled by 1/8)
    uint32_t qhi[8][4];
    {
        const float* qr0 = Qg + (size_t)(q0 + wq + g) * HS;
        const float* qr1 = qr0 + 8 * HS;
        #pragma unroll
        for (int ks = 0; ks < 8; ks++) {
            qhi[ks][0] = __float_as_uint(qr0[8 * ks + tg]);
            qhi[ks][1] = __float_as_uint(qr1[8 * ks + tg]);
            qhi[ks][2] = __float_as_uint(qr0[8 * ks + tg + 4]);
            qhi[ks][3] = __float_as_uint(qr1[8 * ks + tg + 4]);
        }
    }

    float m0r = -1e30f, m1r = -1e30f, l0r = 0.f, l1r = 0.f;
    float o[8][4];
    #pragma unroll
    for (int nt = 0; nt < 8; nt++)
        #pragma unroll
        for (int q = 0; q < 4; q++) o[nt][q] = 0.f;

    const int nkt = 2 * qt + 2;
    for (int kt = 0; kt < nkt; kt++) {
        const int k0 = kt * 64;
        __syncthreads();   // all warps done reading previous tile

        // Direct cp.async of pre-split tiles (16 x 16B per thread)
        #pragma unroll
        for (int i = 0; i < 4; i++) {
            const int lin = tid + 256 * i;
            const int row = lin >> 4;
            const int c4 = (lin & 15) * 4;
            const size_t gs = (size_t)(k0 + row) * HS + c4;
            const uint32_t ko = (uint32_t)(row * KST + c4) * 4;
            const uint32_t vo = (uint32_t)(row * VST + c4) * 4;
            cp_async16(khi_b + ko, Khg + gs);
            cp_async16(klo_b + ko, Klg + gs);
            cp_async16(vhi_b + vo, Vhg + gs);
            cp_async16(vlo_b + vo, Vlg + gs);
        }
        CP_COMMIT();
        CP_WAIT(0);
        __syncthreads();

        // ---- S = Q @ K^T : qhi*(khi + klo) ----
        float sc[8][4];
        #pragma unroll
        for (int nt = 0; nt < 8; nt++)
            #pragma unroll
            for (int q = 0; q < 4; q++) sc[nt][q] = 0.f;

        #pragma unroll
        for (int nt = 0; nt < 8; nt++) {
            const int krow = (nt * 8 + g) * KST;
            #pragma unroll
            for (int ks = 0; ks < 8; ks++) {
                uint32_t bh_[2], bl_[2];
                bh_[0] = __float_as_uint(Khi[krow + 8 * ks + tg]);
                bh_[1] = __float_as_uint(Khi[krow + 8 * ks + tg + 4]);
                bl_[0] = __float_as_uint(Klo[krow + 8 * ks + tg]);
                bl_[1] = __float_as_uint(Klo[krow + 8 * ks + tg + 4]);
                mma_tf32(sc[nt], qhi[ks], bh_);
                mma_tf32(sc[nt], qhi[ks], bl_);
            }
        }

        // ---- causal mask ----
        const int r0 = q0 + wq + g;
        const int r1 = r0 + 8;
        if (k0 + 63 > r0) {
            #pragma unroll
            for (int nt = 0; nt < 8; nt++) {
                const int c = k0 + nt * 8 + 2 * tg;
                if (c > r0)     sc[nt][0] = -1e30f;
                if (c + 1 > r0) sc[nt][1] = -1e30f;
                if (c > r1)     sc[nt][2] = -1e30f;
                if (c + 1 > r1) sc[nt][3] = -1e30f;
            }
        }

        // ---- online softmax (quad shfl) ----
        float mx0 = -1e30f, mx1 = -1e30f;
        #pragma unroll
        for (int nt = 0; nt < 8; nt++) {
            mx0 = fmaxf(mx0, fmaxf(sc[nt][0], sc[nt][1]));
            mx1 = fmaxf(mx1, fmaxf(sc[nt][2], sc[nt][3]));
        }
        mx0 = fmaxf(mx0, __shfl_xor_sync(0xffffffffu, mx0, 1));
        mx0 = fmaxf(mx0, __shfl_xor_sync(0xffffffffu, mx0, 2));
        mx1 = fmaxf(mx1, __shfl_xor_sync(0xffffffffu, mx1, 1));
        mx1 = fmaxf(mx1, __shfl_xor_sync(0xffffffffu, mx1, 2));
        const float mn0 = fmaxf(m0r, mx0);
        const float mn1 = fmaxf(m1r, mx1);

        float su0 = 0.f, su1 = 0.f;
        #pragma unroll
        for (int nt = 0; nt < 8; nt++) {
            sc[nt][0] = __expf(sc[nt][0] - mn0);
            sc[nt][1] = __expf(sc[nt][1] - mn0);
            sc[nt][2] = __expf(sc[nt][2] - mn1);
            sc[nt][3] = __expf(sc[nt][3] - mn1);
            su0 += sc[nt][0] + sc[nt][1];
            su1 += sc[nt][2] + sc[nt][3];
        }
        su0 += __shfl_xor_sync(0xffffffffu, su0, 1);
        su0 += __shfl_xor_sync(0xffffffffu, su0, 2);
        su1 += __shfl_xor_sync(0xffffffffu, su1, 1);
        su1 += __shfl_xor_sync(0xffffffffu, su1, 2);

        const float al0 = __expf(m0r - mn0);
        const float al1 = __expf(m1r - mn1);
        l0r = l0r * al0 + su0;
        l1r = l1r * al1 + su1;
        m0r = mn0;
        m1r = mn1;

        #pragma unroll
        for (int nt = 0; nt < 8; nt++) {
            o[nt][0] *= al0;
            o[nt][1] *= al0;
            o[nt][2] *= al1;
            o[nt][3] *= al1;
        }

        // ---- P relay through warp-private smem slab ----
        float* pr0 = Ps + (wq + g) * PST;
        float* pr1 = Ps + (wq + g + 8) * PST;
        #pragma unroll
        for (int nt = 0; nt < 8; nt++) {
            *(float2*)(pr0 + 8 * nt + 2 * tg) = make_float2(sc[nt][0], sc[nt][1]);
            *(float2*)(pr1 + 8 * nt + 2 * tg) = make_float2(sc[nt][2], sc[nt][3]);
        }
        __syncwarp();

        // ---- O += P @ V : phi*(vhi + vlo) ----
        #pragma unroll
        for (int ks = 0; ks < 8; ks++) {
            uint32_t phi[4];
            phi[0] = tf32_of(pr0[8 * ks + tg]);
            phi[1] = tf32_of(pr1[8 * ks + tg]);
            phi[2] = tf32_of(pr0[8 * ks + tg + 4]);
            phi[3] = tf32_of(pr1[8 * ks + tg + 4]);
            const int vr0 = (8 * ks + tg) * VST;
            const int vr1 = (8 * ks + tg + 4) * VST;
            #pragma unroll
            for (int nt = 0; nt < 8; nt++) {
                uint32_t bh_[2], bl_[2];
                bh_[0] = __float_as_uint(Vhi[vr0 + 8 * nt + g]);
                bh_[1] = __float_as_uint(Vhi[vr1 + 8 * nt + g]);
                bl_[0] = __float_as_uint(Vlo[vr0 + 8 * nt + g]);
                bl_[1] = __float_as_uint(Vlo[vr1 + 8 * nt + g]);
                mma_tf32(o[nt], phi, bh_);
                mma_tf32(o[nt], phi, bl_);
            }
        }
        __syncwarp();
    }

    // ---- epilogue ----
    const int b_ = bh >> 4, h = bh & 15;
    const float inv0 = 1.f / l0r;
    const float inv1 = 1.f / l1r;
    const int t0 = q0 + wq + g;
    const int t1 = t0 + 8;
    float* o0 = out + ((size_t)(b_ * TT + t0)) * CC + h * HS;
    float* o1 = out + ((size_t)(b_ * TT + t1)) * CC + h * HS;
    #pragma unroll
    for (int nt = 0; nt < 8; nt++) {
        *(float2*)(o0 + 8 * nt + 2 * tg) = make_float2(o[nt][0] * inv0, o[nt][1] * inv0);
        *(float2*)(o1 + 8 * nt + 2 * tg) = make_float2(o[nt][2] * inv1, o[nt][3] * inv1);
    }
}

// ===========================================================================
extern "C" void kernel_launch(void* const* d_in, const int* in_sizes, int n_in,
                              void* d_out, int out_size)
{
    const float* x    = (const float*)d_in[0];  // [B,T,C]
    const float* W    = (const float*)d_in[1];  // [3C,C]
    const float* bias = (const float*)d_in[2];  // [3C]
    float* out = (float*)d_out;                 // [B,T,C]

    cudaFuncSetAttribute(qkv_gemm_mma, cudaFuncAttributeMaxDynamicSharedMemorySize,
                         GEMM_SMEM);
    cudaFuncSetAttribute(attn_mma, cudaFuncAttributeMaxDynamicSharedMemorySize,
                         ATTN_SMEM);

    presplit_kernel<<<(NX + NW) / 4 / 256, 256>>>(x, W);

    dim3 g1(NROWS / 128, M3C / 128);   // (32, 24)
    qkv_gemm_mma<<<g1, 256, GEMM_SMEM>>>(bias);

    dim3 g2(TT / 128, BB * HH);        // (16, 32)
    attn_mma<<<g2, 256, ATTN_SMEM>>>(out);
}

// round 12
// speedup vs baseline: 1.1869x; 1.1869x over previous
#include <cuda_runtime.h>
#include <cuda_bf16.h>
#include <cstdint>

// Problem constants
#define BB 2
#define TT 2048
#define CC 1024
#define HH 16
#define HS 64
#define NROWS (BB*TT)   // 4096
#define M3C  (3*CC)     // 3072
#define NX (NROWS*CC)
#define NW (M3C*CC)
#define NQKV (BB*HH*TT*HS)

// Q/K/V stored as packed bf16x2 hi/lo (same total bytes as fp32)
__device__ uint32_t g_qhi[NQKV/2], g_qlo[NQKV/2];
__device__ uint32_t g_khi[NQKV/2], g_klo[NQKV/2];
__device__ uint32_t g_vhi[NQKV/2], g_vlo[NQKV/2];
// GEMM presplit operands (tf32, as in R10)
__device__ float g_xhi[NX];
__device__ float g_whi[NW], g_wlo[NW];

// ===========================================================================
// Helpers (plain-sm_100-legal PTX)
// ===========================================================================
__device__ __forceinline__ uint32_t smem_u32(const void* p) {
    uint32_t a;
    asm("{ .reg .u64 t; cvta.to.shared.u64 t, %1; cvt.u32.u64 %0, t; }"
        : "=r"(a) : "l"(p));
    return a;
}
__device__ __forceinline__ void cp_async16(uint32_t dst, const void* src) {
    asm volatile("cp.async.cg.shared.global [%0], [%1], 16;"
                 :: "r"(dst), "l"(src));
}
#define CP_COMMIT() asm volatile("cp.async.commit_group;" ::: "memory")
#define CP_WAIT(n)  asm volatile("cp.async.wait_group %0;" :: "n"(n) : "memory")

__device__ __forceinline__ uint32_t tf32_of(float x) {
    uint32_t u;
    asm("cvt.rna.tf32.f32 %0, %1;" : "=r"(u) : "f"(x));
    return u;
}
__device__ __forceinline__ void split_tf32_f(float x, float& hi, float& lo) {
    uint32_t h;
    asm("cvt.rna.tf32.f32 %0, %1;" : "=r"(h) : "f"(x));
    hi = __uint_as_float(h);
    float r = x - hi;
    uint32_t l;
    asm("cvt.rna.tf32.f32 %0, %1;" : "=r"(l) : "f"(r));
    lo = __uint_as_float(l);
}
// tf32 MMA (GEMM)
__device__ __forceinline__ void mma_tf32(float d[4], const uint32_t a[4],
                                         const uint32_t b[2]) {
    asm volatile(
        "mma.sync.aligned.m16n8k8.row.col.f32.tf32.tf32.f32 "
        "{%0,%1,%2,%3}, {%4,%5,%6,%7}, {%8,%9}, {%0,%1,%2,%3};"
        : "+f"(d[0]), "+f"(d[1]), "+f"(d[2]), "+f"(d[3])
        : "r"(a[0]), "r"(a[1]), "r"(a[2]), "r"(a[3]),
          "r"(b[0]), "r"(b[1]));
}
// bf16 MMA (attention)
__device__ __forceinline__ void mma_bf16(float d[4], const uint32_t a[4],
                                         uint32_t b0, uint32_t b1) {
    asm volatile(
        "mma.sync.aligned.m16n8k16.row.col.f32.bf16.bf16.f32 "
        "{%0,%1,%2,%3}, {%4,%5,%6,%7}, {%8,%9}, {%0,%1,%2,%3};"
        : "+f"(d[0]), "+f"(d[1]), "+f"(d[2]), "+f"(d[3])
        : "r"(a[0]), "r"(a[1]), "r"(a[2]), "r"(a[3]), "r"(b0), "r"(b1));
}
__device__ __forceinline__ void ldsm_x4(uint32_t r[4], uint32_t addr) {
    asm volatile("ldmatrix.sync.aligned.m8n8.x4.shared.b16 {%0,%1,%2,%3}, [%4];"
        : "=r"(r[0]), "=r"(r[1]), "=r"(r[2]), "=r"(r[3]) : "r"(addr));
}
__device__ __forceinline__ void ldsm_x4_t(uint32_t r[4], uint32_t addr) {
    asm volatile("ldmatrix.sync.aligned.m8n8.x4.trans.shared.b16 {%0,%1,%2,%3}, [%4];"
        : "=r"(r[0]), "=r"(r[1]), "=r"(r[2]), "=r"(r[3]) : "r"(addr));
}
// pack two f32 -> bf16x2 (e0 in low half = first k element)
__device__ __forceinline__ uint32_t packbf(float e0, float e1) {
    uint32_t r;
    asm("cvt.rn.bf16x2.f32 %0, %1, %2;" : "=r"(r) : "f"(e1), "f"(e0));
    return r;
}
__device__ __forceinline__ float bf16rt(float x) {   // round-trip to bf16
    return __bfloat162float(__float2bfloat16_rn(x));
}

// ===========================================================================
// Kernel 0: pre-split GEMM operands. x -> tf32 hi only; W -> tf32 hi + lo.
// ===========================================================================
__global__ __launch_bounds__(256) void presplit_kernel(
    const float* __restrict__ x, const float* __restrict__ W)
{
    const size_t i4 = (size_t)blockIdx.x * 256 + threadIdx.x;
    if (i4 < NX / 4) {
        float4 v = ((const float4*)x)[i4];
        float4 h;
        h.x = __uint_as_float(tf32_of(v.x));
        h.y = __uint_as_float(tf32_of(v.y));
        h.z = __uint_as_float(tf32_of(v.z));
        h.w = __uint_as_float(tf32_of(v.w));
        ((float4*)g_xhi)[i4] = h;
    } else {
        const size_t off = i4 - NX / 4;
        float4 v = ((const float4*)W)[off];
        float4 h, l;
        split_tf32_f(v.x, h.x, l.x);
        split_tf32_f(v.y, h.y, l.y);
        split_tf32_f(v.z, h.z, l.z);
        split_tf32_f(v.w, h.w, l.w);
        ((float4*)g_whi)[off] = h;
        ((float4*)g_wlo)[off] = l;
    }
}

// ===========================================================================
// Kernel 1: QKV projection (R10 mainloop, tf32 2-pass, 2 CTAs/SM).
// Epilogue writes Q/K/V as packed bf16x2 hi/lo (same bytes as fp32).
// ===========================================================================
#define GST 36
#define GBUF (128 * GST)
#define GEMM_SMEM (2 * 3 * GBUF * 4)      // 110592 bytes

__global__ __launch_bounds__(256, 2) void qkv_gemm_mma(const float* __restrict__ bias)
{
    extern __shared__ float sm[];
    const int tid = threadIdx.x, lane = tid & 31, warp = tid >> 5;
    const int wm = warp & 1, wn = warp >> 1;
    const int g = lane >> 2, tg = lane & 3;
    const int m0 = blockIdx.x * 128;
    const int n0 = blockIdx.y * 128;

    int r_[4], c_[4];
    #pragma unroll
    for (int i = 0; i < 4; i++) {
        int idx = tid + 256 * i;
        r_[i] = idx >> 3;
        c_[i] = (idx & 7) * 4;
    }
    const uint32_t smbase = smem_u32(sm);

    float acc[4][4][4];
    #pragma unroll
    for (int mt = 0; mt < 4; mt++)
        #pragma unroll
        for (int nt = 0; nt < 4; nt++)
            #pragma unroll
            for (int q = 0; q < 4; q++) acc[mt][nt][q] = 0.f;

    #define GEMM_ISSUE(ch) do { \
        const uint32_t _bs = smbase + ((ch) & 1) * (3 * GBUF) * 4; \
        const size_t _ko = (size_t)(ch) * 32; \
        const float* _xh = g_xhi + (size_t)m0 * CC + _ko; \
        const float* _wh = g_whi + (size_t)n0 * CC + _ko; \
        const float* _wl = g_wlo + (size_t)n0 * CC + _ko; \
        _Pragma("unroll") \
        for (int i = 0; i < 4; i++) { \
            const uint32_t _o = (uint32_t)(r_[i] * GST + c_[i]) * 4; \
            const size_t _s = (size_t)r_[i] * CC + c_[i]; \
            cp_async16(_bs + _o,                _xh + _s); \
            cp_async16(_bs + GBUF * 4 + _o,     _wh + _s); \
            cp_async16(_bs + 2 * GBUF * 4 + _o, _wl + _s); \
        } \
        CP_COMMIT(); \
    } while (0)

    GEMM_ISSUE(0);

    for (int ch = 0; ch < 32; ch++) {
        if (ch < 31) { GEMM_ISSUE(ch + 1); CP_WAIT(1); }
        else         { CP_WAIT(0); }
        __syncthreads();

        const float* Ah = sm + (ch & 1) * (3 * GBUF);
        const float* Bh = Ah + GBUF;
        const float* Bl = Ah + 2 * GBUF;

        #pragma unroll
        for (int ks = 0; ks < 4; ks++) {
            const int k0 = ks * 8;
            uint32_t ahi[4][4], bhi[4][2], blo[4][2];
            #pragma unroll
            for (int mt = 0; mt < 4; mt++) {
                const int rb = (wm * 64 + mt * 16 + g) * GST + k0 + tg;
                ahi[mt][0] = __float_as_uint(Ah[rb]);
                ahi[mt][1] = __float_as_uint(Ah[rb + 8 * GST]);
                ahi[mt][2] = __float_as_uint(Ah[rb + 4]);
                ahi[mt][3] = __float_as_uint(Ah[rb + 8 * GST + 4]);
            }
            #pragma unroll
            for (int nt = 0; nt < 4; nt++) {
                const int cb = (wn * 32 + nt * 8 + g) * GST + k0 + tg;
                bhi[nt][0] = __float_as_uint(Bh[cb]);
                bhi[nt][1] = __float_as_uint(Bh[cb + 4]);
                blo[nt][0] = __float_as_uint(Bl[cb]);
                blo[nt][1] = __float_as_uint(Bl[cb + 4]);
            }
            #pragma unroll
            for (int mt = 0; mt < 4; mt++)
                #pragma unroll
                for (int nt = 0; nt < 4; nt++) {
                    mma_tf32(acc[mt][nt], ahi[mt], bhi[nt]);
                    mma_tf32(acc[mt][nt], ahi[mt], blo[nt]);
                }
        }
        __syncthreads();
    }

    // Epilogue: bias (+ Q scale), split to bf16 hi/lo, pack, scatter.
    const int part = blockIdx.y >> 3;       // 0=q 1=k 2=v
    uint32_t* dhi = (part == 0) ? g_qhi : (part == 1) ? g_khi : g_vhi;
    uint32_t* dlo = (part == 0) ? g_qlo : (part == 1) ? g_klo : g_vlo;
    const float scl = (part == 0) ? 0.125f : 1.0f;

    #pragma unroll
    for (int nt = 0; nt < 4; nt++) {
        const int n = n0 + wn * 32 + nt * 8 + 2 * tg;
        const int h = (n >> 6) & 15;
        const int d = n & 63;
        const float bb0 = __ldg(bias + n);
        const float bb1 = __ldg(bias + n + 1);
        #pragma unroll
        for (int mt = 0; mt < 4; mt++) {
            #pragma unroll
            for (int half = 0; half < 2; half++) {
                const int m = m0 + wm * 64 + mt * 16 + g + 8 * half;
                const int bi = m >> 11, t = m & 2047;
                const size_t ix2 = ((((size_t)(bi * HH + h)) * TT + t) * HS + d) >> 1;
                const float s0 = (acc[mt][nt][2 * half]     + bb0) * scl;
                const float s1 = (acc[mt][nt][2 * half + 1] + bb1) * scl;
                const float h0 = bf16rt(s0), h1 = bf16rt(s1);
                dhi[ix2] = packbf(h0, h1);
                dlo[ix2] = packbf(s0 - h0, s1 - h1);
            }
        }
    }
}

// ===========================================================================
// Kernel 2: causal flash attention, bf16 m16n8k16 3-pass + ldmatrix.
// CTA = 128 q-rows of one (b,h); 8 warps x m16 slab; key tiles of 64.
// smem rows padded to 144B (bank-rotation 4/row -> conflict-free LDSM).
// P relayed in registers (C-frag == A-frag layout for m16n8k16).
// ===========================================================================
#define QRW 36                 // u32 per smem row (144 B)
#define Q_TILE (128 * QRW)     // 4608 u32
#define KV_TILE (64 * QRW)     // 2304 u32
#define ATTN_SMEM ((2 * Q_TILE + 4 * KV_TILE) * 4)   // 73728 B

__global__ __launch_bounds__(256, 2) void attn_mma(float* __restrict__ out)
{
    extern __shared__ uint32_t asm_[];
    uint32_t* Qh = asm_;
    uint32_t* Ql = Qh + Q_TILE;
    uint32_t* Kh = Ql + Q_TILE;
    uint32_t* Kl = Kh + KV_TILE;
    uint32_t* Vh = Kl + KV_TILE;
    uint32_t* Vl = Vh + KV_TILE;

    const int tid = threadIdx.x, lane = tid & 31, wid = tid >> 5;
    const int g = lane >> 2, tg = lane & 3;
    const int qt = 15 - blockIdx.x;          // heavy CTAs first
    const int bh = blockIdx.y;
    const int q0 = qt * 128;
    const int wq = wid * 16;

    const uint32_t* Qhg = g_qhi + (size_t)bh * (TT * HS / 2);
    const uint32_t* Qlg = g_qlo + (size_t)bh * (TT * HS / 2);
    const uint32_t* Khg = g_khi + (size_t)bh * (TT * HS / 2);
    const uint32_t* Klg = g_klo + (size_t)bh * (TT * HS / 2);
    const uint32_t* Vhg = g_vhi + (size_t)bh * (TT * HS / 2);
    const uint32_t* Vlg = g_vlo + (size_t)bh * (TT * HS / 2);

    const uint32_t qh_b = smem_u32(Qh), ql_b = smem_u32(Ql);
    const uint32_t kh_b = smem_u32(Kh), kl_b = smem_u32(Kl);
    const uint32_t vh_b = smem_u32(Vh), vl_b = smem_u32(Vl);

    // Per-lane ldmatrix offsets (bytes)
    const int lane7 = lane & 7, laneg = lane >> 3;
    const uint32_t qoff = (uint32_t)((wq + ((laneg & 1) << 3) + lane7) * 144
                                     + (lane >> 4) * 16);
    const uint32_t koff = (uint32_t)(lane7 * 144 + laneg * 16);
    const uint32_t voff = (uint32_t)(lane * 144);

    // Load Q tile (hi+lo) once: rows q0..q0+127, 8x16B per thread
    #pragma unroll
    for (int i = 0; i < 4; i++) {
        const int c = tid + 256 * i;
        const int row = c >> 3, k8 = c & 7;
        const size_t gofs = (size_t)(q0 + row) * 32 + k8 * 4;
        const uint32_t sofs = (uint32_t)(row * 144 + k8 * 16);
        cp_async16(qh_b + sofs, Qhg + gofs);
        cp_async16(ql_b + sofs, Qlg + gofs);
    }
    CP_COMMIT();

    float m0r = -1e30f, m1r = -1e30f, l0r = 0.f, l1r = 0.f;
    float o[8][4];
    #pragma unroll
    for (int nt = 0; nt < 8; nt++)
        #pragma unroll
        for (int q = 0; q < 4; q++) o[nt][q] = 0.f;

    const int nkt = 2 * qt + 2;
    for (int kt = 0; kt < nkt; kt++) {
        const int k0 = kt * 64;
        __syncthreads();   // prior tile readers done

        // K/V tiles (hi+lo): 8x16B per thread
        #pragma unroll
        for (int i = 0; i < 2; i++) {
            const int c = tid + 256 * i;
            const int row = c >> 3, k8 = c & 7;
            const size_t gofs = (size_t)(k0 + row) * 32 + k8 * 4;
            const uint32_t sofs = (uint32_t)(row * 144 + k8 * 16);
            cp_async16(kh_b + sofs, Khg + gofs);
            cp_async16(kl_b + sofs, Klg + gofs);
            cp_async16(vh_b + sofs, Vhg + gofs);
            cp_async16(vl_b + sofs, Vlg + gofs);
        }
        CP_COMMIT();
        CP_WAIT(0);
        __syncthreads();

        // ---- S = Q @ K^T : 3-pass bf16 ----
        float sc[8][4];
        #pragma unroll
        for (int nt = 0; nt < 8; nt++)
            #pragma unroll
            for (int q = 0; q < 4; q++) sc[nt][q] = 0.f;

        #pragma unroll
        for (int p = 0; p < 2; p++) {       // kspair: d-blocks 32p..32p+31
            uint32_t ah[2][4], al[2][4];
            #pragma unroll
            for (int ksl = 0; ksl < 2; ksl++) {
                const uint32_t qa = qoff + (uint32_t)((2 * p + ksl) * 32);
                ldsm_x4(ah[ksl], qh_b + qa);
                ldsm_x4(al[ksl], ql_b + qa);
            }
            #pragma unroll
            for (int nt = 0; nt < 8; nt++) {
                uint32_t kh[4], kl[4];
                const uint32_t ka = (uint32_t)(nt * 8 * 144 + p * 64) + koff;
                ldsm_x4(kh, kh_b + ka);
                ldsm_x4(kl, kl_b + ka);
                mma_bf16(sc[nt], ah[0], kh[0], kh[1]);
                mma_bf16(sc[nt], ah[0], kl[0], kl[1]);
                mma_bf16(sc[nt], al[0], kh[0], kh[1]);
                mma_bf16(sc[nt], ah[1], kh[2], kh[3]);
                mma_bf16(sc[nt], ah[1], kl[2], kl[3]);
                mma_bf16(sc[nt], al[1], kh[2], kh[3]);
            }
        }

        // ---- causal mask ----
        const int r0 = q0 + wq + g;
        const int r1 = r0 + 8;
        if (k0 + 63 > r0) {
            #pragma unroll
            for (int nt = 0; nt < 8; nt++) {
                const int c = k0 + nt * 8 + 2 * tg;
                if (c > r0)     sc[nt][0] = -1e30f;
                if (c + 1 > r0) sc[nt][1] = -1e30f;
                if (c > r1)     sc[nt][2] = -1e30f;
                if (c + 1 > r1) sc[nt][3] = -1e30f;
            }
        }

        // ---- online softmax (quad shfl) ----
        float mx0 = -1e30f, mx1 = -1e30f;
        #pragma unroll
        for (int nt = 0; nt < 8; nt++) {
            mx0 = fmaxf(mx0, fmaxf(sc[nt][0], sc[nt][1]));
            mx1 = fmaxf(mx1, fmaxf(sc[nt][2], sc[nt][3]));
        }
        mx0 = fmaxf(mx0, __shfl_xor_sync(0xffffffffu, mx0, 1));
        mx0 = fmaxf(mx0, __shfl_xor_sync(0xffffffffu, mx0, 2));
        mx1 = fmaxf(mx1, __shfl_xor_sync(0xffffffffu, mx1, 1));
        mx1 = fmaxf(mx1, __shfl_xor_sync(0xffffffffu, mx1, 2));
        const float mn0 = fmaxf(m0r, mx0);
        const float mn1 = fmaxf(m1r, mx1);

        float su0 = 0.f, su1 = 0.f;
        #pragma unroll
        for (int nt = 0; nt < 8; nt++) {
            sc[nt][0] = __expf(sc[nt][0] - mn0);
            sc[nt][1] = __expf(sc[nt][1] - mn0);
            sc[nt][2] = __expf(sc[nt][2] - mn1);
            sc[nt][3] = __expf(sc[nt][3] - mn1);
            su0 += sc[nt][0] + sc[nt][1];
            su1 += sc[nt][2] + sc[nt][3];
        }
        su0 += __shfl_xor_sync(0xffffffffu, su0, 1);
        su0 += __shfl_xor_sync(0xffffffffu, su0, 2);
        su1 += __shfl_xor_sync(0xffffffffu, su1, 1);
        su1 += __shfl_xor_sync(0xffffffffu, su1, 2);

        const float al0 = __expf(m0r - mn0);
        const float al1 = __expf(m1r - mn1);
        l0r = l0r * al0 + su0;
        l1r = l1r * al1 + su1;
        m0r = mn0;
        m1r = mn1;

        #pragma unroll
        for (int nt = 0; nt < 8; nt++) {
            o[nt][0] *= al0;
            o[nt][1] *= al0;
            o[nt][2] *= al1;
            o[nt][3] *= al1;
        }

        // ---- O += P @ V : 3-pass bf16, P split in registers ----
        #pragma unroll
        for (int p = 0; p < 2; p++) {       // keys 32p..32p+31
            uint32_t ph[2][4], pl[2][4];
            #pragma unroll
            for (int ksl = 0; ksl < 2; ksl++) {
                const int n0_ = 2 * (2 * p + ksl);      // QK nt blocks
                const int n1_ = n0_ + 1;
                float h00 = bf16rt(sc[n0_][0]), h01 = bf16rt(sc[n0_][1]);
                float h02 = bf16rt(sc[n0_][2]), h03 = bf16rt(sc[n0_][3]);
                float h10 = bf16rt(sc[n1_][0]), h11 = bf16rt(sc[n1_][1]);
                float h12 = bf16rt(sc[n1_][2]), h13 = bf16rt(sc[n1_][3]);
                ph[ksl][0] = packbf(h00, h01);
                ph[ksl][1] = packbf(h02, h03);
                ph[ksl][2] = packbf(h10, h11);
                ph[ksl][3] = packbf(h12, h13);
                pl[ksl][0] = packbf(sc[n0_][0] - h00, sc[n0_][1] - h01);
                pl[ksl][1] = packbf(sc[n0_][2] - h02, sc[n0_][3] - h03);
                pl[ksl][2] = packbf(sc[n1_][0] - h10, sc[n1_][1] - h11);
                pl[ksl][3] = packbf(sc[n1_][2] - h12, sc[n1_][3] - h13);
            }
            #pragma unroll
            for (int nt = 0; nt < 8; nt++) {
                uint32_t vh[4], vl[4];
                const uint32_t va = (uint32_t)(p * 32 * 144 + nt * 16) + voff;
                ldsm_x4_t(vh, vh_b + va);
                ldsm_x4_t(vl, vl_b + va);
                mma_bf16(o[nt], ph[0], vh[0], vh[1]);
                mma_bf16(o[nt], ph[0], vl[0], vl[1]);
                mma_bf16(o[nt], pl[0], vh[0], vh[1]);
                mma_bf16(o[nt], ph[1], vh[2], vh[3]);
                mma_bf16(o[nt], ph[1], vl[2], vl[3]);
                mma_bf16(o[nt], pl[1], vh[2], vh[3]);
            }
        }
    }

    // ---- epilogue ----
    const int b_ = bh >> 4, h = bh & 15;
    const float inv0 = 1.f / l0r;
    const float inv1 = 1.f / l1r;
    const int t0 = q0 + wq + g;
    const int t1 = t0 + 8;
    float* o0 = out + ((size_t)(b_ * TT + t0)) * CC + h * HS;
    float* o1 = out + ((size_t)(b_ * TT + t1)) * CC + h * HS;
    #pragma unroll
    for (int nt = 0; nt < 8; nt++) {
        *(float2*)(o0 + 8 * nt + 2 * tg) = make_float2(o[nt][0] * inv0, o[nt][1] * inv0);
        *(float2*)(o1 + 8 * nt + 2 * tg) = make_float2(o[nt][2] * inv1, o[nt][3] * inv1);
    }
}

// ===========================================================================
extern "C" void kernel_launch(void* const* d_in, const int* in_sizes, int n_in,
                              void* d_out, int out_size)
{
    const float* x    = (const float*)d_in[0];  // [B,T,C]
    const float* W    = (const float*)d_in[1];  // [3C,C]
    const float* bias = (const float*)d_in[2];  // [3C]
    float* out = (float*)d_out;                 // [B,T,C]

    cudaFuncSetAttribute(qkv_gemm_mma, cudaFuncAttributeMaxDynamicSharedMemorySize,
                         GEMM_SMEM);
    cudaFuncSetAttribute(attn_mma, cudaFuncAttributeMaxDynamicSharedMemorySize,
                         ATTN_SMEM);

    presplit_kernel<<<(NX + NW) / 4 / 256, 256>>>(x, W);

    dim3 g1(NROWS / 128, M3C / 128);   // (32, 24)
    qkv_gemm_mma<<<g1, 256, GEMM_SMEM>>>(bias);

    dim3 g2(TT / 128, BB * HH);        // (16, 32)
    attn_mma<<<g2, 256, ATTN_SMEM>>>(out);
}

// round 13
// speedup vs baseline: 1.3137x; 1.1068x over previous
#include <cuda_runtime.h>
#include <cuda_bf16.h>
#include <cstdint>

// Problem constants
#define BB 2
#define TT 2048
#define CC 1024
#define HH 16
#define HS 64
#define NROWS (BB*TT)   // 4096
#define M3C  (3*CC)     // 3072
#define NX (NROWS*CC)
#define NW (M3C*CC)
#define NQKV (BB*HH*TT*HS)

// Q/K/V packed bf16x2 hi/lo
__device__ uint32_t g_qhi[NQKV/2], g_qlo[NQKV/2];
__device__ uint32_t g_khi[NQKV/2], g_klo[NQKV/2];
__device__ uint32_t g_vhi[NQKV/2], g_vlo[NQKV/2];
// GEMM operands packed bf16x2 hi/lo
__device__ uint32_t g_xh[NX/2], g_xl[NX/2];
__device__ uint32_t g_wh[NW/2], g_wl[NW/2];

// ===========================================================================
// Helpers
// ===========================================================================
__device__ __forceinline__ uint32_t smem_u32(const void* p) {
    uint32_t a;
    asm("{ .reg .u64 t; cvta.to.shared.u64 t, %1; cvt.u32.u64 %0, t; }"
        : "=r"(a) : "l"(p));
    return a;
}
__device__ __forceinline__ void cp_async16(uint32_t dst, const void* src) {
    asm volatile("cp.async.cg.shared.global [%0], [%1], 16;"
                 :: "r"(dst), "l"(src));
}
#define CP_COMMIT() asm volatile("cp.async.commit_group;" ::: "memory")
#define CP_WAIT(n)  asm volatile("cp.async.wait_group %0;" :: "n"(n) : "memory")

__device__ __forceinline__ void mma_bf16(float d[4], const uint32_t a[4],
                                         uint32_t b0, uint32_t b1) {
    asm volatile(
        "mma.sync.aligned.m16n8k16.row.col.f32.bf16.bf16.f32 "
        "{%0,%1,%2,%3}, {%4,%5,%6,%7}, {%8,%9}, {%0,%1,%2,%3};"
        : "+f"(d[0]), "+f"(d[1]), "+f"(d[2]), "+f"(d[3])
        : "r"(a[0]), "r"(a[1]), "r"(a[2]), "r"(a[3]), "r"(b0), "r"(b1));
}
__device__ __forceinline__ void ldsm_x4(uint32_t r[4], uint32_t addr) {
    asm volatile("ldmatrix.sync.aligned.m8n8.x4.shared.b16 {%0,%1,%2,%3}, [%4];"
        : "=r"(r[0]), "=r"(r[1]), "=r"(r[2]), "=r"(r[3]) : "r"(addr));
}
__device__ __forceinline__ void ldsm_x4_t(uint32_t r[4], uint32_t addr) {
    asm volatile("ldmatrix.sync.aligned.m8n8.x4.trans.shared.b16 {%0,%1,%2,%3}, [%4];"
        : "=r"(r[0]), "=r"(r[1]), "=r"(r[2]), "=r"(r[3]) : "r"(addr));
}
__device__ __forceinline__ uint32_t packbf(float e0, float e1) {
    uint32_t r;
    asm("cvt.rn.bf16x2.f32 %0, %1, %2;" : "=r"(r) : "f"(e1), "f"(e0));
    return r;
}
__device__ __forceinline__ float bf16rt(float x) {
    return __bfloat162float(__float2bfloat16_rn(x));
}

// ===========================================================================
// Kernel 0: pre-split x and W into packed bf16x2 hi/lo (4 B/value total).
// ===========================================================================
__global__ __launch_bounds__(256) void presplit_kernel(
    const float* __restrict__ x, const float* __restrict__ W)
{
    const size_t i4 = (size_t)blockIdx.x * 256 + threadIdx.x;
    const float4* src;
    uint2 *dhi, *dlo;
    size_t off;
    if (i4 < NX / 4) {
        src = (const float4*)x;
        dhi = (uint2*)g_xh;  dlo = (uint2*)g_xl;
        off = i4;
    } else {
        src = (const float4*)W;
        dhi = (uint2*)g_wh;  dlo = (uint2*)g_wl;
        off = i4 - NX / 4;
    }
    float4 v = src[off];
    const float h0 = bf16rt(v.x), h1 = bf16rt(v.y);
    const float h2 = bf16rt(v.z), h3 = bf16rt(v.w);
    uint2 hh, ll;
    hh.x = packbf(h0, h1);
    hh.y = packbf(h2, h3);
    ll.x = packbf(v.x - h0, v.y - h1);
    ll.y = packbf(v.z - h2, v.w - h3);
    dhi[off] = hh;
    dlo[off] = ll;
}

// ===========================================================================
// Kernel 1: QKV projection, bf16 m16n8k16 3-pass + ldmatrix.
// 128x128 CTA tile, K-chunk 32, 8 warps (2x4), warp tile 64x32.
// smem rows 80 B (64 B data + 16 pad) -> conflict-free LDSM. 2 CTAs/SM.
// ===========================================================================
#define GRW 20                         // u32 per smem row (80 B)
#define GTILE (128 * GRW)              // 2560 u32 per matrix-half
#define GSTAGE (4 * GTILE)             // Ah,Al,Bh,Bl
#define GEMM_SMEM (2 * GSTAGE * 4)     // 81920 bytes

__global__ __launch_bounds__(256, 2) void qkv_gemm_mma(const float* __restrict__ bias)
{
    extern __shared__ uint32_t gsm[];
    const int tid = threadIdx.x, lane = tid & 31, warp = tid >> 5;
    const int wm = warp & 1, wn = warp >> 1;   // warp grid 2 x 4
    const int g = lane >> 2, tg = lane & 3;
    const int m0 = blockIdx.x * 128;
    const int n0 = blockIdx.y * 128;

    const uint32_t smb = smem_u32(gsm);
    const int lane7 = lane & 7, laneg = lane >> 3;
    // A-frag address pattern (mirrors attention qoff), stride 80 B
    const uint32_t aoff = (uint32_t)((((laneg & 1) << 3) + lane7) * 80
                                     + (lane >> 4) * 16);
    // B-frag address pattern (mirrors attention koff)
    const uint32_t boff = (uint32_t)(lane7 * 80 + laneg * 16);

    float acc[4][4][4];
    #pragma unroll
    for (int mt = 0; mt < 4; mt++)
        #pragma unroll
        for (int nt = 0; nt < 4; nt++)
            #pragma unroll
            for (int q = 0; q < 4; q++) acc[mt][nt][q] = 0.f;

    // per-thread cp.async coords: 2 x 16B per matrix-half per chunk
    // slot c in 0..511: row = c>>2 (0..127), seg = c&3 (16B within 64B row)
    #define GEMM_ISSUE(ch) do { \
        const uint32_t _bs = smb + ((ch) & 1) * (GSTAGE * 4); \
        const uint32_t* _xh = g_xh + (size_t)m0 * (CC/2) + (ch) * 16; \
        const uint32_t* _xl = g_xl + (size_t)m0 * (CC/2) + (ch) * 16; \
        const uint32_t* _wh = g_wh + (size_t)n0 * (CC/2) + (ch) * 16; \
        const uint32_t* _wl = g_wl + (size_t)n0 * (CC/2) + (ch) * 16; \
        _Pragma("unroll") \
        for (int _i = 0; _i < 2; _i++) { \
            const int _c = tid + 256 * _i; \
            const int _row = _c >> 2, _seg = _c & 3; \
            const uint32_t _so = (uint32_t)(_row * 80 + _seg * 16); \
            const size_t _go = (size_t)_row * (CC/2) + _seg * 4; \
            cp_async16(_bs + _so,                 _xh + _go); \
            cp_async16(_bs + GTILE * 4 + _so,     _xl + _go); \
            cp_async16(_bs + 2 * GTILE * 4 + _so, _wh + _go); \
            cp_async16(_bs + 3 * GTILE * 4 + _so, _wl + _go); \
        } \
        CP_COMMIT(); \
    } while (0)

    GEMM_ISSUE(0);

    for (int ch = 0; ch < 32; ch++) {
        if (ch < 31) { GEMM_ISSUE(ch + 1); CP_WAIT(1); }
        else         { CP_WAIT(0); }
        __syncthreads();

        const uint32_t ah_b = smb + (ch & 1) * (GSTAGE * 4);
        const uint32_t al_b = ah_b + GTILE * 4;
        const uint32_t bh_b = ah_b + 2 * GTILE * 4;
        const uint32_t bl_b = ah_b + 3 * GTILE * 4;

        // B fragments for the whole chunk (k0..31): 4 regs per nt
        uint32_t bh[4][4], bl[4][4];
        #pragma unroll
        for (int nt = 0; nt < 4; nt++) {
            const uint32_t ba = (uint32_t)((wn * 32 + nt * 8) * 80) + boff;
            ldsm_x4(bh[nt], bh_b + ba);
            ldsm_x4(bl[nt], bl_b + ba);
        }

        #pragma unroll
        for (int p = 0; p < 2; p++) {          // k16 slices
            #pragma unroll
            for (int mt = 0; mt < 4; mt++) {
                uint32_t ah[4], al[4];
                const uint32_t aa = (uint32_t)((wm * 64 + mt * 16) * 80 + p * 32)
                                    + aoff;
                ldsm_x4(ah, ah_b + aa);
                ldsm_x4(al, al_b + aa);
                #pragma unroll
                for (int nt = 0; nt < 4; nt++) {
                    mma_bf16(acc[mt][nt], ah, bh[nt][2*p], bh[nt][2*p+1]);
                    mma_bf16(acc[mt][nt], ah, bl[nt][2*p], bl[nt][2*p+1]);
                    mma_bf16(acc[mt][nt], al, bh[nt][2*p], bh[nt][2*p+1]);
                }
            }
        }
        __syncthreads();
    }

    // Epilogue: bias (+ Q scale), split to bf16 hi/lo, pack, scatter.
    const int part = blockIdx.y >> 3;       // 0=q 1=k 2=v
    uint32_t* dhi = (part == 0) ? g_qhi : (part == 1) ? g_khi : g_vhi;
    uint32_t* dlo = (part == 0) ? g_qlo : (part == 1) ? g_klo : g_vlo;
    const float scl = (part == 0) ? 0.125f : 1.0f;

    #pragma unroll
    for (int nt = 0; nt < 4; nt++) {
        const int n = n0 + wn * 32 + nt * 8 + 2 * tg;
        const int h = (n >> 6) & 15;
        const int d = n & 63;
        const float bb0 = __ldg(bias + n);
        const float bb1 = __ldg(bias + n + 1);
        #pragma unroll
        for (int mt = 0; mt < 4; mt++) {
            #pragma unroll
            for (int half = 0; half < 2; half++) {
                const int m = m0 + wm * 64 + mt * 16 + g + 8 * half;
                const int bi = m >> 11, t = m & 2047;
                const size_t ix2 = ((((size_t)(bi * HH + h)) * TT + t) * HS + d) >> 1;
                const float s0 = (acc[mt][nt][2 * half]     + bb0) * scl;
                const float s1 = (acc[mt][nt][2 * half + 1] + bb1) * scl;
                const float h0 = bf16rt(s0), h1 = bf16rt(s1);
                dhi[ix2] = packbf(h0, h1);
                dlo[ix2] = packbf(s0 - h0, s1 - h1);
            }
        }
    }
}

// ===========================================================================
// Kernel 2: causal flash attention, bf16 m16n8k16 3-pass + ldmatrix.
// (byte-identical to Round 12 — passed, ~300us)
// ===========================================================================
#define QRW 36                 // u32 per smem row (144 B)
#define Q_TILE (128 * QRW)
#define KV_TILE (64 * QRW)
#define ATTN_SMEM ((2 * Q_TILE + 4 * KV_TILE) * 4)   // 73728 B

__global__ __launch_bounds__(256, 2) void attn_mma(float* __restrict__ out)
{
    extern __shared__ uint32_t asm_[];
    uint32_t* Qh = asm_;
    uint32_t* Ql = Qh + Q_TILE;
    uint32_t* Kh = Ql + Q_TILE;
    uint32_t* Kl = Kh + KV_TILE;
    uint32_t* Vh = Kl + KV_TILE;
    uint32_t* Vl = Vh + KV_TILE;

    const int tid = threadIdx.x, lane = tid & 31, wid = tid >> 5;
    const int g = lane >> 2, tg = lane & 3;
    const int qt = 15 - blockIdx.x;          // heavy CTAs first
    const int bh = blockIdx.y;
    const int q0 = qt * 128;
    const int wq = wid * 16;

    const uint32_t* Qhg = g_qhi + (size_t)bh * (TT * HS / 2);
    const uint32_t* Qlg = g_qlo + (size_t)bh * (TT * HS / 2);
    const uint32_t* Khg = g_khi + (size_t)bh * (TT * HS / 2);
    const uint32_t* Klg = g_klo + (size_t)bh * (TT * HS / 2);
    const uint32_t* Vhg = g_vhi + (size_t)bh * (TT * HS / 2);
    const uint32_t* Vlg = g_vlo + (size_t)bh * (TT * HS / 2);

    const uint32_t qh_b = smem_u32(Qh), ql_b = smem_u32(Ql);
    const uint32_t kh_b = smem_u32(Kh), kl_b = smem_u32(Kl);
    const uint32_t vh_b = smem_u32(Vh), vl_b = smem_u32(Vl);

    const int lane7 = lane & 7, laneg = lane >> 3;
    const uint32_t qoff = (uint32_t)((wq + ((laneg & 1) << 3) + lane7) * 144
                                     + (lane >> 4) * 16);
    const uint32_t koff = (uint32_t)(lane7 * 144 + laneg * 16);
    const uint32_t voff = (uint32_t)(lane * 144);

    #pragma unroll
    for (int i = 0; i < 4; i++) {
        const int c = tid + 256 * i;
        const int row = c >> 3, k8 = c & 7;
        const size_t gofs = (size_t)(q0 + row) * 32 + k8 * 4;
        const uint32_t sofs = (uint32_t)(row * 144 + k8 * 16);
        cp_async16(qh_b + sofs, Qhg + gofs);
        cp_async16(ql_b + sofs, Qlg + gofs);
    }
    CP_COMMIT();

    float m0r = -1e30f, m1r = -1e30f, l0r = 0.f, l1r = 0.f;
    float o[8][4];
    #pragma unroll
    for (int nt = 0; nt < 8; nt++)
        #pragma unroll
        for (int q = 0; q < 4; q++) o[nt][q] = 0.f;

    const int nkt = 2 * qt + 2;
    for (int kt = 0; kt < nkt; kt++) {
        const int k0 = kt * 64;
        __syncthreads();

        #pragma unroll
        for (int i = 0; i < 2; i++) {
            const int c = tid + 256 * i;
            const int row = c >> 3, k8 = c & 7;
            const size_t gofs = (size_t)(k0 + row) * 32 + k8 * 4;
            const uint32_t sofs = (uint32_t)(row * 144 + k8 * 16);
            cp_async16(kh_b + sofs, Khg + gofs);
            cp_async16(kl_b + sofs, Klg + gofs);
            cp_async16(vh_b + sofs, Vhg + gofs);
            cp_async16(vl_b + sofs, Vlg + gofs);
        }
        CP_COMMIT();
        CP_WAIT(0);
        __syncthreads();

        float sc[8][4];
        #pragma unroll
        for (int nt = 0; nt < 8; nt++)
            #pragma unroll
            for (int q = 0; q < 4; q++) sc[nt][q] = 0.f;

        #pragma unroll
        for (int p = 0; p < 2; p++) {
            uint32_t ah[2][4], al[2][4];
            #pragma unroll
            for (int ksl = 0; ksl < 2; ksl++) {
                const uint32_t qa = qoff + (uint32_t)((2 * p + ksl) * 32);
                ldsm_x4(ah[ksl], qh_b + qa);
                ldsm_x4(al[ksl], ql_b + qa);
            }
            #pragma unroll
            for (int nt = 0; nt < 8; nt++) {
                uint32_t kh[4], kl[4];
                const uint32_t ka = (uint32_t)(nt * 8 * 144 + p * 64) + koff;
                ldsm_x4(kh, kh_b + ka);
                ldsm_x4(kl, kl_b + ka);
                mma_bf16(sc[nt], ah[0], kh[0], kh[1]);
                mma_bf16(sc[nt], ah[0], kl[0], kl[1]);
                mma_bf16(sc[nt], al[0], kh[0], kh[1]);
                mma_bf16(sc[nt], ah[1], kh[2], kh[3]);
                mma_bf16(sc[nt], ah[1], kl[2], kl[3]);
                mma_bf16(sc[nt], al[1], kh[2], kh[3]);
            }
        }

        const int r0 = q0 + wq + g;
        const int r1 = r0 + 8;
        if (k0 + 63 > r0) {
            #pragma unroll
            for (int nt = 0; nt < 8; nt++) {
                const int c = k0 + nt * 8 + 2 * tg;
                if (c > r0)     sc[nt][0] = -1e30f;
                if (c + 1 > r0) sc[nt][1] = -1e30f;
                if (c > r1)     sc[nt][2] = -1e30f;
                if (c + 1 > r1) sc[nt][3] = -1e30f;
            }
        }

        float mx0 = -1e30f, mx1 = -1e30f;
        #pragma unroll
        for (int nt = 0; nt < 8; nt++) {
            mx0 = fmaxf(mx0, fmaxf(sc[nt][0], sc[nt][1]));
            mx1 = fmaxf(mx1, fmaxf(sc[nt][2], sc[nt][3]));
        }
        mx0 = fmaxf(mx0, __shfl_xor_sync(0xffffffffu, mx0, 1));
        mx0 = fmaxf(mx0, __shfl_xor_sync(0xffffffffu, mx0, 2));
        mx1 = fmaxf(mx1, __shfl_xor_sync(0xffffffffu, mx1, 1));
        mx1 = fmaxf(mx1, __shfl_xor_sync(0xffffffffu, mx1, 2));
        const float mn0 = fmaxf(m0r, mx0);
        const float mn1 = fmaxf(m1r, mx1);

        float su0 = 0.f, su1 = 0.f;
        #pragma unroll
        for (int nt = 0; nt < 8; nt++) {
            sc[nt][0] = __expf(sc[nt][0] - mn0);
            sc[nt][1] = __expf(sc[nt][1] - mn0);
            sc[nt][2] = __expf(sc[nt][2] - mn1);
            sc[nt][3] = __expf(sc[nt][3] - mn1);
            su0 += sc[nt][0] + sc[nt][1];
            su1 += sc[nt][2] + sc[nt][3];
        }
        su0 += __shfl_xor_sync(0xffffffffu, su0, 1);
        su0 += __shfl_xor_sync(0xffffffffu, su0, 2);
        su1 += __shfl_xor_sync(0xffffffffu, su1, 1);
        su1 += __shfl_xor_sync(0xffffffffu, su1, 2);

        const float al0 = __expf(m0r - mn0);
        const float al1 = __expf(m1r - mn1);
        l0r = l0r * al0 + su0;
        l1r = l1r * al1 + su1;
        m0r = mn0;
        m1r = mn1;

        #pragma unroll
        for (int nt = 0; nt < 8; nt++) {
            o[nt][0] *= al0;
            o[nt][1] *= al0;
            o[nt][2] *= al1;
            o[nt][3] *= al1;
        }

        #pragma unroll
        for (int p = 0; p < 2; p++) {
            uint32_t ph[2][4], pl[2][4];
            #pragma unroll
            for (int ksl = 0; ksl < 2; ksl++) {
                const int n0_ = 2 * (2 * p + ksl);
                const int n1_ = n0_ + 1;
                float h00 = bf16rt(sc[n0_][0]), h01 = bf16rt(sc[n0_][1]);
                float h02 = bf16rt(sc[n0_][2]), h03 = bf16rt(sc[n0_][3]);
                float h10 = bf16rt(sc[n1_][0]), h11 = bf16rt(sc[n1_][1]);
                float h12 = bf16rt(sc[n1_][2]), h13 = bf16rt(sc[n1_][3]);
                ph[ksl][0] = packbf(h00, h01);
                ph[ksl][1] = packbf(h02, h03);
                ph[ksl][2] = packbf(h10, h11);
                ph[ksl][3] = packbf(h12, h13);
                pl[ksl][0] = packbf(sc[n0_][0] - h00, sc[n0_][1] - h01);
                pl[ksl][1] = packbf(sc[n0_][2] - h02, sc[n0_][3] - h03);
                pl[ksl][2] = packbf(sc[n1_][0] - h10, sc[n1_][1] - h11);
                pl[ksl][3] = packbf(sc[n1_][2] - h12, sc[n1_][3] - h13);
            }
            #pragma unroll
            for (int nt = 0; nt < 8; nt++) {
                uint32_t vh[4], vl[4];
                const uint32_t va = (uint32_t)(p * 32 * 144 + nt * 16) + voff;
                ldsm_x4_t(vh, vh_b + va);
                ldsm_x4_t(vl, vl_b + va);
                mma_bf16(o[nt], ph[0], vh[0], vh[1]);
                mma_bf16(o[nt], ph[0], vl[0], vl[1]);
                mma_bf16(o[nt], pl[0], vh[0], vh[1]);
                mma_bf16(o[nt], ph[1], vh[2], vh[3]);
                mma_bf16(o[nt], ph[1], vl[2], vl[3]);
                mma_bf16(o[nt], pl[1], vh[2], vh[3]);
            }
        }
    }

    const int b_ = bh >> 4, h = bh & 15;
    const float inv0 = 1.f / l0r;
    const float inv1 = 1.f / l1r;
    const int t0 = q0 + wq + g;
    const int t1 = t0 + 8;
    float* o0 = out + ((size_t)(b_ * TT + t0)) * CC + h * HS;
    float* o1 = out + ((size_t)(b_ * TT + t1)) * CC + h * HS;
    #pragma unroll
    for (int nt = 0; nt < 8; nt++) {
        *(float2*)(o0 + 8 * nt + 2 * tg) = make_float2(o[nt][0] * inv0, o[nt][1] * inv0);
        *(float2*)(o1 + 8 * nt + 2 * tg) = make_float2(o[nt][2] * inv1, o[nt][3] * inv1);
    }
}

// ===========================================================================
extern "C" void kernel_launch(void* const* d_in, const int* in_sizes, int n_in,
                              void* d_out, int out_size)
{
    const float* x    = (const float*)d_in[0];  // [B,T,C]
    const float* W    = (const float*)d_in[1];  // [3C,C]
    const float* bias = (const float*)d_in[2];  // [3C]
    float* out = (float*)d_out;                 // [B,T,C]

    cudaFuncSetAttribute(qkv_gemm_mma, cudaFuncAttributeMaxDynamicSharedMemorySize,
                         GEMM_SMEM);
    cudaFuncSetAttribute(attn_mma, cudaFuncAttributeMaxDynamicSharedMemorySize,
                         ATTN_SMEM);

    presplit_kernel<<<(NX + NW) / 4 / 256, 256>>>(x, W);

    dim3 g1(NROWS / 128, M3C / 128);   // (32, 24)
    qkv_gemm_mma<<<g1, 256, GEMM_SMEM>>>(bias);

    dim3 g2(TT / 128, BB * HH);        // (16, 32)
    attn_mma<<<g2, 256, ATTN_SMEM>>>(out);
}

// round 15
// speedup vs baseline: 1.8697x; 1.4232x over previous
#include <cuda_runtime.h>
#include <cuda_fp16.h>
#include <cstdint>

// Problem constants
#define BB 2
#define TT 2048
#define CC 1024
#define HH 16
#define HS 64
#define NROWS (BB*TT)   // 4096
#define M3C  (3*CC)     // 3072
#define NX (NROWS*CC)
#define NW (M3C*CC)
#define NQKV (BB*HH*TT*HS)

// Q (fp16 hi only), K/V (fp16 hi+lo), packed f16x2
__device__ uint32_t g_qh[NQKV/2];
__device__ uint32_t g_kh[NQKV/2], g_kl[NQKV/2];
__device__ uint32_t g_vh[NQKV/2], g_vl[NQKV/2];
// GEMM operands: x fp16 hi only; W fp16 hi+lo
__device__ uint32_t g_xh[NX/2];
__device__ uint32_t g_wh[NW/2], g_wl[NW/2];

// ===========================================================================
// Helpers
// ===========================================================================
__device__ __forceinline__ uint32_t smem_u32(const void* p) {
    uint32_t a;
    asm("{ .reg .u64 t; cvta.to.shared.u64 t, %1; cvt.u32.u64 %0, t; }"
        : "=r"(a) : "l"(p));
    return a;
}
__device__ __forceinline__ void cp_async16(uint32_t dst, const void* src) {
    asm volatile("cp.async.cg.shared.global [%0], [%1], 16;"
                 :: "r"(dst), "l"(src));
}
#define CP_COMMIT() asm volatile("cp.async.commit_group;" ::: "memory")
#define CP_WAIT(n)  asm volatile("cp.async.wait_group %0;" :: "n"(n) : "memory")

__device__ __forceinline__ void mma_f16(float d[4], const uint32_t a[4],
                                        uint32_t b0, uint32_t b1) {
    asm volatile(
        "mma.sync.aligned.m16n8k16.row.col.f32.f16.f16.f32 "
        "{%0,%1,%2,%3}, {%4,%5,%6,%7}, {%8,%9}, {%0,%1,%2,%3};"
        : "+f"(d[0]), "+f"(d[1]), "+f"(d[2]), "+f"(d[3])
        : "r"(a[0]), "r"(a[1]), "r"(a[2]), "r"(a[3]), "r"(b0), "r"(b1));
}
__device__ __forceinline__ void ldsm_x4(uint32_t r[4], uint32_t addr) {
    asm volatile("ldmatrix.sync.aligned.m8n8.x4.shared.b16 {%0,%1,%2,%3}, [%4];"
        : "=r"(r[0]), "=r"(r[1]), "=r"(r[2]), "=r"(r[3]) : "r"(addr));
}
__device__ __forceinline__ void ldsm_x4_t(uint32_t r[4], uint32_t addr) {
    asm volatile("ldmatrix.sync.aligned.m8n8.x4.trans.shared.b16 {%0,%1,%2,%3}, [%4];"
        : "=r"(r[0]), "=r"(r[1]), "=r"(r[2]), "=r"(r[3]) : "r"(addr));
}
// pack two f32 -> f16x2 (e0 in low half)
__device__ __forceinline__ uint32_t packf16(float e0, float e1) {
    uint32_t r;
    asm("cvt.rn.f16x2.f32 %0, %1, %2;" : "=r"(r) : "f"(e1), "f"(e0));
    return r;
}
__device__ __forceinline__ float f16rt(float x) {   // round-trip to fp16
    return __half2float(__float2half_rn(x));
}

// ===========================================================================
// Kernel 0: pre-split. x -> fp16 hi; W -> fp16 hi + lo.
// ===========================================================================
__global__ __launch_bounds__(256) void presplit_kernel(
    const float* __restrict__ x, const float* __restrict__ W)
{
    const size_t i4 = (size_t)blockIdx.x * 256 + threadIdx.x;
    if (i4 < NX / 4) {
        float4 v = ((const float4*)x)[i4];
        uint2 hh;
        hh.x = packf16(f16rt(v.x), f16rt(v.y));
        hh.y = packf16(f16rt(v.z), f16rt(v.w));
        ((uint2*)g_xh)[i4] = hh;
    } else {
        const size_t off = i4 - NX / 4;
        float4 v = ((const float4*)W)[off];
        const float h0 = f16rt(v.x), h1 = f16rt(v.y);
        const float h2 = f16rt(v.z), h3 = f16rt(v.w);
        uint2 hh, ll;
        hh.x = packf16(h0, h1);
        hh.y = packf16(h2, h3);
        ll.x = packf16(v.x - h0, v.y - h1);
        ll.y = packf16(v.z - h2, v.w - h3);
        ((uint2*)g_wh)[off] = hh;
        ((uint2*)g_wl)[off] = ll;
    }
}

// ===========================================================================
// Kernel 1: QKV projection, fp16 m16n8k16 2-pass:  acc = xh*(Wh + Wl).
// 128x128 CTA tile, K-chunk 32, 8 warps (2x4), warp tile 64x32.
// smem rows 80 B -> conflict-free LDSM. 3 buffers/stage, 2 CTAs/SM.
// ===========================================================================
#define GRW 20
#define GTILE (128 * GRW)              // 2560 u32
#define GSTAGE (3 * GTILE)             // Ah, Bh, Bl
#define GEMM_SMEM (2 * GSTAGE * 4)     // 61440 bytes

__global__ __launch_bounds__(256, 2) void qkv_gemm_mma(const float* __restrict__ bias)
{
    extern __shared__ uint32_t gsm[];
    const int tid = threadIdx.x, lane = tid & 31, warp = tid >> 5;
    const int wm = warp & 1, wn = warp >> 1;
    const int g = lane >> 2, tg = lane & 3;
    const int m0 = blockIdx.x * 128;
    const int n0 = blockIdx.y * 128;

    const uint32_t smb = smem_u32(gsm);
    const int lane7 = lane & 7, laneg = lane >> 3;
    const uint32_t aoff = (uint32_t)((((laneg & 1) << 3) + lane7) * 80
                                     + (lane >> 4) * 16);
    const uint32_t boff = (uint32_t)(lane7 * 80 + laneg * 16);

    float acc[4][4][4];
    #pragma unroll
    for (int mt = 0; mt < 4; mt++)
        #pragma unroll
        for (int nt = 0; nt < 4; nt++)
            #pragma unroll
            for (int q = 0; q < 4; q++) acc[mt][nt][q] = 0.f;

    #define GEMM_ISSUE(ch) do { \
        const uint32_t _bs = smb + ((ch) & 1) * (GSTAGE * 4); \
        const uint32_t* _xh = g_xh + (size_t)m0 * (CC/2) + (ch) * 16; \
        const uint32_t* _wh = g_wh + (size_t)n0 * (CC/2) + (ch) * 16; \
        const uint32_t* _wl = g_wl + (size_t)n0 * (CC/2) + (ch) * 16; \
        _Pragma("unroll") \
        for (int _i = 0; _i < 2; _i++) { \
            const int _c = tid + 256 * _i; \
            const int _row = _c >> 2, _seg = _c & 3; \
            const uint32_t _so = (uint32_t)(_row * 80 + _seg * 16); \
            const size_t _go = (size_t)_row * (CC/2) + _seg * 4; \
            cp_async16(_bs + _so,                 _xh + _go); \
            cp_async16(_bs + GTILE * 4 + _so,     _wh + _go); \
            cp_async16(_bs + 2 * GTILE * 4 + _so, _wl + _go); \
        } \
        CP_COMMIT(); \
    } while (0)

    GEMM_ISSUE(0);

    for (int ch = 0; ch < 32; ch++) {
        if (ch < 31) { GEMM_ISSUE(ch + 1); CP_WAIT(1); }
        else         { CP_WAIT(0); }
        __syncthreads();

        const uint32_t ah_b = smb + (ch & 1) * (GSTAGE * 4);
        const uint32_t bh_b = ah_b + GTILE * 4;
        const uint32_t bl_b = ah_b + 2 * GTILE * 4;

        uint32_t bh[4][4], bl[4][4];
        #pragma unroll
        for (int nt = 0; nt < 4; nt++) {
            const uint32_t ba = (uint32_t)((wn * 32 + nt * 8) * 80) + boff;
            ldsm_x4(bh[nt], bh_b + ba);
            ldsm_x4(bl[nt], bl_b + ba);
        }

        #pragma unroll
        for (int p = 0; p < 2; p++) {
            #pragma unroll
            for (int mt = 0; mt < 4; mt++) {
                uint32_t ah[4];
                const uint32_t aa = (uint32_t)((wm * 64 + mt * 16) * 80 + p * 32)
                                    + aoff;
                ldsm_x4(ah, ah_b + aa);
                #pragma unroll
                for (int nt = 0; nt < 4; nt++) {
                    mma_f16(acc[mt][nt], ah, bh[nt][2*p], bh[nt][2*p+1]);
                    mma_f16(acc[mt][nt], ah, bl[nt][2*p], bl[nt][2*p+1]);
                }
            }
        }
        __syncthreads();
    }

    // Epilogue: bias (+ Q scale); Q -> fp16 hi only; K/V -> fp16 hi+lo.
    const int part = blockIdx.y >> 3;       // 0=q 1=k 2=v
    const float scl = (part == 0) ? 0.125f : 1.0f;

    #pragma unroll
    for (int nt = 0; nt < 4; nt++) {
        const int n = n0 + wn * 32 + nt * 8 + 2 * tg;
        const int h = (n >> 6) & 15;
        const int d = n & 63;
        const float bb0 = __ldg(bias + n);
        const float bb1 = __ldg(bias + n + 1);
        #pragma unroll
        for (int mt = 0; mt < 4; mt++) {
            #pragma unroll
            for (int half = 0; half < 2; half++) {
                const int m = m0 + wm * 64 + mt * 16 + g + 8 * half;
                const int bi = m >> 11, t = m & 2047;
                const size_t ix2 = ((((size_t)(bi * HH + h)) * TT + t) * HS + d) >> 1;
                const float s0 = (acc[mt][nt][2 * half]     + bb0) * scl;
                const float s1 = (acc[mt][nt][2 * half + 1] + bb1) * scl;
                const float h0 = f16rt(s0), h1 = f16rt(s1);
                if (part == 0) {
                    g_qh[ix2] = packf16(h0, h1);
                } else if (part == 1) {
                    g_kh[ix2] = packf16(h0, h1);
                    g_kl[ix2] = packf16(s0 - h0, s1 - h1);
                } else {
                    g_vh[ix2] = packf16(h0, h1);
                    g_vl[ix2] = packf16(s0 - h0, s1 - h1);
                }
            }
        }
    }
}

// ===========================================================================
// Kernel 2: causal flash attention, fp16 m16n8k16 2-pass + ldmatrix.
//   S = qh*(kh + kl);  O += ph*(vh + vl).  (R13 structure, Ql/Pl removed.)
// ===========================================================================
#define QRW 36                 // u32 per smem row (144 B)
#define Q_TILE (128 * QRW)
#define KV_TILE (64 * QRW)
#define ATTN_SMEM ((Q_TILE + 4 * KV_TILE) * 4)   // 55296 B

__global__ __launch_bounds__(256, 2) void attn_mma(float* __restrict__ out)
{
    extern __shared__ uint32_t asm_[];
    uint32_t* Qh = asm_;
    uint32_t* Kh = Qh + Q_TILE;
    uint32_t* Kl = Kh + KV_TILE;
    uint32_t* Vh = Kl + KV_TILE;
    uint32_t* Vl = Vh + KV_TILE;

    const int tid = threadIdx.x, lane = tid & 31, wid = tid >> 5;
    const int g = lane >> 2, tg = lane & 3;
    const int qt = 15 - blockIdx.x;          // heavy CTAs first
    const int bh = blockIdx.y;
    const int q0 = qt * 128;
    const int wq = wid * 16;

    const uint32_t* Qhg = g_qh + (size_t)bh * (TT * HS / 2);
    const uint32_t* Khg = g_kh + (size_t)bh * (TT * HS / 2);
    const uint32_t* Klg = g_kl + (size_t)bh * (TT * HS / 2);
    const uint32_t* Vhg = g_vh + (size_t)bh * (TT * HS / 2);
    const uint32_t* Vlg = g_vl + (size_t)bh * (TT * HS / 2);

    const uint32_t qh_b = smem_u32(Qh);
    const uint32_t kh_b = smem_u32(Kh), kl_b = smem_u32(Kl);
    const uint32_t vh_b = smem_u32(Vh), vl_b = smem_u32(Vl);

    const int lane7 = lane & 7, laneg = lane >> 3;
    const uint32_t qoff = (uint32_t)((wq + ((laneg & 1) << 3) + lane7) * 144
                                     + (lane >> 4) * 16);
    const uint32_t koff = (uint32_t)(lane7 * 144 + laneg * 16);
    const uint32_t voff = (uint32_t)(lane * 144);

    // Load Q tile (hi only): 4 x 16B per thread
    #pragma unroll
    for (int i = 0; i < 4; i++) {
        const int c = tid + 256 * i;
        const int row = c >> 3, k8 = c & 7;
        cp_async16(qh_b + (uint32_t)(row * 144 + k8 * 16),
                   Qhg + (size_t)(q0 + row) * 32 + k8 * 4);
    }
    CP_COMMIT();

    float m0r = -1e30f, m1r = -1e30f, l0r = 0.f, l1r = 0.f;
    float o[8][4];
    #pragma unroll
    for (int nt = 0; nt < 8; nt++)
        #pragma unroll
        for (int q = 0; q < 4; q++) o[nt][q] = 0.f;

    const int nkt = 2 * qt + 2;
    for (int kt = 0; kt < nkt; kt++) {
        const int k0 = kt * 64;
        __syncthreads();

        #pragma unroll
        for (int i = 0; i < 2; i++) {
            const int c = tid + 256 * i;
            const int row = c >> 3, k8 = c & 7;
            const size_t gofs = (size_t)(k0 + row) * 32 + k8 * 4;
            const uint32_t sofs = (uint32_t)(row * 144 + k8 * 16);
            cp_async16(kh_b + sofs, Khg + gofs);
            cp_async16(kl_b + sofs, Klg + gofs);
            cp_async16(vh_b + sofs, Vhg + gofs);
            cp_async16(vl_b + sofs, Vlg + gofs);
        }
        CP_COMMIT();
        CP_WAIT(0);
        __syncthreads();

        // ---- S = Q @ K^T : qh*(kh + kl) ----
        float sc[8][4];
        #pragma unroll
        for (int nt = 0; nt < 8; nt++)
            #pragma unroll
            for (int q = 0; q < 4; q++) sc[nt][q] = 0.f;

        #pragma unroll
        for (int p = 0; p < 2; p++) {
            uint32_t ah[2][4];
            #pragma unroll
            for (int ksl = 0; ksl < 2; ksl++)
                ldsm_x4(ah[ksl], qh_b + qoff + (uint32_t)((2 * p + ksl) * 32));
            #pragma unroll
            for (int nt = 0; nt < 8; nt++) {
                uint32_t kh[4], kl[4];
                const uint32_t ka = (uint32_t)(nt * 8 * 144 + p * 64) + koff;
                ldsm_x4(kh, kh_b + ka);
                ldsm_x4(kl, kl_b + ka);
                mma_f16(sc[nt], ah[0], kh[0], kh[1]);
                mma_f16(sc[nt], ah[0], kl[0], kl[1]);
                mma_f16(sc[nt], ah[1], kh[2], kh[3]);
                mma_f16(sc[nt], ah[1], kl[2], kl[3]);
            }
        }

        // ---- causal mask ----
        const int r0 = q0 + wq + g;
        const int r1 = r0 + 8;
        if (k0 + 63 > r0) {
            #pragma unroll
            for (int nt = 0; nt < 8; nt++) {
                const int c = k0 + nt * 8 + 2 * tg;
                if (c > r0)     sc[nt][0] = -1e30f;
                if (c + 1 > r0) sc[nt][1] = -1e30f;
                if (c > r1)     sc[nt][2] = -1e30f;
                if (c + 1 > r1) sc[nt][3] = -1e30f;
            }
        }

        // ---- online softmax (quad shfl) ----
        float mx0 = -1e30f, mx1 = -1e30f;
        #pragma unroll
        for (int nt = 0; nt < 8; nt++) {
            mx0 = fmaxf(mx0, fmaxf(sc[nt][0], sc[nt][1]));
            mx1 = fmaxf(mx1, fmaxf(sc[nt][2], sc[nt][3]));
        }
        mx0 = fmaxf(mx0, __shfl_xor_sync(0xffffffffu, mx0, 1));
        mx0 = fmaxf(mx0, __shfl_xor_sync(0xffffffffu, mx0, 2));
        mx1 = fmaxf(mx1, __shfl_xor_sync(0xffffffffu, mx1, 1));
        mx1 = fmaxf(mx1, __shfl_xor_sync(0xffffffffu, mx1, 2));
        const float mn0 = fmaxf(m0r, mx0);
        const float mn1 = fmaxf(m1r, mx1);

        float su0 = 0.f, su1 = 0.f;
        #pragma unroll
        for (int nt = 0; nt < 8; nt++) {
            sc[nt][0] = __expf(sc[nt][0] - mn0);
            sc[nt][1] = __expf(sc[nt][1] - mn0);
            sc[nt][2] = __expf(sc[nt][2] - mn1);
            sc[nt][3] = __expf(sc[nt][3] - mn1);
            su0 += sc[nt][0] + sc[nt][1];
            su1 += sc[nt][2] + sc[nt][3];
        }
        su0 += __shfl_xor_sync(0xffffffffu, su0, 1);
        su0 += __shfl_xor_sync(0xffffffffu, su0, 2);
        su1 += __shfl_xor_sync(0xffffffffu, su1, 1);
        su1 += __shfl_xor_sync(0xffffffffu, su1, 2);

        const float al0 = __expf(m0r - mn0);
        const float al1 = __expf(m1r - mn1);
        l0r = l0r * al0 + su0;
        l1r = l1r * al1 + su1;
        m0r = mn0;
        m1r = mn1;

        #pragma unroll
        for (int nt = 0; nt < 8; nt++) {
            o[nt][0] *= al0;
            o[nt][1] *= al0;
            o[nt][2] *= al1;
            o[nt][3] *= al1;
        }

        // ---- O += P @ V : ph*(vh + vl), P packed in registers ----
        #pragma unroll
        for (int p = 0; p < 2; p++) {
            uint32_t ph[2][4];
            #pragma unroll
            for (int ksl = 0; ksl < 2; ksl++) {
                const int n0_ = 2 * (2 * p + ksl);
                const int n1_ = n0_ + 1;
                ph[ksl][0] = packf16(sc[n0_][0], sc[n0_][1]);
                ph[ksl][1] = packf16(sc[n0_][2], sc[n0_][3]);
                ph[ksl][2] = packf16(sc[n1_][0], sc[n1_][1]);
                ph[ksl][3] = packf16(sc[n1_][2], sc[n1_][3]);
            }
            #pragma unroll
            for (int nt = 0; nt < 8; nt++) {
                uint32_t vh[4], vl[4];
                const uint32_t va = (uint32_t)(p * 32 * 144 + nt * 16) + voff;
                ldsm_x4_t(vh, vh_b + va);
                ldsm_x4_t(vl, vl_b + va);
                mma_f16(o[nt], ph[0], vh[0], vh[1]);
                mma_f16(o[nt], ph[0], vl[0], vl[1]);
                mma_f16(o[nt], ph[1], vh[2], vh[3]);
                mma_f16(o[nt], ph[1], vl[2], vl[3]);
            }
        }
    }

    // ---- epilogue ----
    const int b_ = bh >> 4, h = bh & 15;
    const float inv0 = 1.f / l0r;
    const float inv1 = 1.f / l1r;
    const int t0 = q0 + wq + g;
    const int t1 = t0 + 8;
    float* o0 = out + ((size_t)(b_ * TT + t0)) * CC + h * HS;
    float* o1 = out + ((size_t)(b_ * TT + t1)) * CC + h * HS;
    #pragma unroll
    for (int nt = 0; nt < 8; nt++) {
        *(float2*)(o0 + 8 * nt + 2 * tg) = make_float2(o[nt][0] * inv0, o[nt][1] * inv0);
        *(float2*)(o1 + 8 * nt + 2 * tg) = make_float2(o[nt][2] * inv1, o[nt][3] * inv1);
    }
}

// ===========================================================================
extern "C" void kernel_launch(void* const* d_in, const int* in_sizes, int n_in,
                              void* d_out, int out_size)
{
    const float* x    = (const float*)d_in[0];  // [B,T,C]
    const float* W    = (const float*)d_in[1];  // [3C,C]
    const float* bias = (const float*)d_in[2];  // [3C]
    float* out = (float*)d_out;                 // [B,T,C]

    cudaFuncSetAttribute(qkv_gemm_mma, cudaFuncAttributeMaxDynamicSharedMemorySize,
                         GEMM_SMEM);
    cudaFuncSetAttribute(attn_mma, cudaFuncAttributeMaxDynamicSharedMemorySize,
                         ATTN_SMEM);

    presplit_kernel<<<(NX + NW) / 4 / 256, 256>>>(x, W);

    dim3 g1(NROWS / 128, M3C / 128);   // (32, 24)
    qkv_gemm_mma<<<g1, 256, GEMM_SMEM>>>(bias);

    dim3 g2(TT / 128, BB * HH);        // (16, 32)
    attn_mma<<<g2, 256, ATTN_SMEM>>>(out);
}